// round 5
// baseline (speedup 1.0000x reference)
#include <cuda_runtime.h>
#include <math.h>
#include <stdint.h>

#define NN   40000
#define NP   40064          // 313 * 128, padded
#define EE   640000
#define FIN  33
#define HH   128
#define LL   8
#define ALPHA 0.1f
#define DEGCAP 64

// ---------------- scratch (no allocation allowed) ----------------
__device__ float g_x0[NP * HH];
__device__ float g_xca[NP * HH];   // xc ping buffer
__device__ float g_xcb[NP * HH];   // xc pong buffer
__device__ int   g_cnt[NN];
__device__ int   g_ecol[(size_t)NN * DEGCAP];
__device__ float g_ew[(size_t)NN * DEGCAP];

// ---------------- input projection: x0 = relu(x @ W_in^T + b_in) ----------------
__global__ void input_proj_kernel(const float* __restrict__ x,
                                  const float* __restrict__ Win,
                                  const float* __restrict__ bin) {
    __shared__ float sW[HH * FIN];
    __shared__ float sx[FIN];
    int tid = threadIdx.x;
    for (int i = tid; i < HH * FIN; i += 128) sW[i] = Win[i];
    float b = bin[tid];
    int row0 = blockIdx.x * 32;
    for (int r = 0; r < 32; r++) {
        int row = row0 + r;
        __syncthreads();
        if (tid < FIN) sx[tid] = x[row * FIN + tid];
        __syncthreads();
        float s = b;
#pragma unroll
        for (int f = 0; f < FIN; f++) s += sW[tid * FIN + f] * sx[f];
        s = fmaxf(s, 0.0f);
        g_x0[row * HH + tid] = s;
        g_xca[row * HH + tid] = s;
    }
}

// ---------------- ELL build ----------------
__global__ void zero_cnt_kernel() {
    int i = blockIdx.x * blockDim.x + threadIdx.x;
    if (i < NN) g_cnt[i] = 0;
}

__global__ void scatter_ell_kernel(const int* __restrict__ er,
                                   const int* __restrict__ ec,
                                   const float* __restrict__ ew) {
    int e = blockIdx.x * blockDim.x + threadIdx.x;
    if (e < EE) {
        int r = er[e];
        int s = atomicAdd(&g_cnt[r], 1);
        if (s < DEGCAP) {
            g_ecol[(size_t)r * DEGCAP + s] = ec[e];
            g_ew[(size_t)r * DEGCAP + s] = ew[e];
        }
    }
}

// ---------------- fused layer: gather(SpMM)+alpha -> smem A; GEMM; GCNII epilogue ----
// Reads ONLY from src buffer (race-free snapshot), writes ONLY to dst buffer.
// CTA: 128 rows, 256 threads = 8 warps. A tile [128][ASTR] fp32 in smem.
// GEMM: warps 4m x 2n (warp tile 32x64), thread tile 8x8, rows interleaved
// (m = m0 + lane_r + 4*rr) for conflict-free smem access. B double-buffered, BK=32.
#define ASTR 136
#define BSTR 136
#define BKC  32
#define SMEM_FUSED ((128 * ASTR + 2 * BKC * BSTR) * 4)

__global__ void __launch_bounds__(256, 2) layer_fused_kernel(const float* __restrict__ src,
                                                             float* __restrict__ dst,
                                                             const float* __restrict__ W,
                                                             float beta) {
    extern __shared__ float sm[];
    float* As = sm;                       // [128][ASTR]
    float* Bs = sm + 128 * ASTR;          // [2][BKC][BSTR]

    int tid = threadIdx.x;
    int wid = tid >> 5, lane = tid & 31;
    int r0 = blockIdx.x * 128;

    // ---------- phase 1: gather rows into A tile (reads src only) ----------
    {
        const float4* xc4 = (const float4*)src;
        int lane4 = lane * 4;
#pragma unroll 2
        for (int p = 0; p < 16; p++) {
            int ml = wid * 16 + p;
            int row = r0 + ml;
            float4 acc = make_float4(0.f, 0.f, 0.f, 0.f);
            if (row < NN) {
                int cn = g_cnt[row];
                cn = cn < DEGCAP ? cn : DEGCAP;
                const int* cb = g_ecol + (size_t)row * DEGCAP;
                const float* wb = g_ew + (size_t)row * DEGCAP;
                float4 acc2 = make_float4(0.f, 0.f, 0.f, 0.f);
                int i = 0;
                for (; i + 2 <= cn; i += 2) {
                    int c0 = cb[i], c1 = cb[i + 1];
                    float w0 = wb[i], w1 = wb[i + 1];
                    float4 v0 = xc4[c0 * 32 + lane];
                    float4 v1 = xc4[c1 * 32 + lane];
                    acc.x += w0 * v0.x; acc.y += w0 * v0.y;
                    acc.z += w0 * v0.z; acc.w += w0 * v0.w;
                    acc2.x += w1 * v1.x; acc2.y += w1 * v1.y;
                    acc2.z += w1 * v1.z; acc2.w += w1 * v1.w;
                }
                if (i < cn) {
                    int c0 = cb[i]; float w0 = wb[i];
                    float4 v0 = xc4[c0 * 32 + lane];
                    acc.x += w0 * v0.x; acc.y += w0 * v0.y;
                    acc.z += w0 * v0.z; acc.w += w0 * v0.w;
                }
                acc.x += acc2.x; acc.y += acc2.y; acc.z += acc2.z; acc.w += acc2.w;
                float4 x0v = ((const float4*)g_x0)[row * 32 + lane];
                acc.x = (1.0f - ALPHA) * acc.x + ALPHA * x0v.x;
                acc.y = (1.0f - ALPHA) * acc.y + ALPHA * x0v.y;
                acc.z = (1.0f - ALPHA) * acc.z + ALPHA * x0v.z;
                acc.w = (1.0f - ALPHA) * acc.w + ALPHA * x0v.w;
            }
            *(float4*)&As[ml * ASTR + lane4] = acc;
        }
    }

    // load B chunk 0 (overlaps with other warps still gathering)
    {
#pragma unroll
        for (int i = 0; i < 4; i++) {
            int idx = tid + i * 256;
            int k = idx >> 5, n4 = idx & 31;
            float4 v = *(const float4*)&W[k * HH + n4 * 4];
            *(float4*)&Bs[k * BSTR + n4 * 4] = v;
        }
    }
    __syncthreads();

    // ---------- phase 2: GEMM ----------
    int wm = wid >> 1, wn = wid & 1;
    int lane_r = lane >> 3, lane_c = lane & 7;
    int m0 = wm * 32, n0 = wn * 64 + lane_c * 8;

    float acc[8][8];
#pragma unroll
    for (int i = 0; i < 8; i++)
#pragma unroll
        for (int j = 0; j < 8; j++) acc[i][j] = 0.f;

#pragma unroll
    for (int c = 0; c < 4; c++) {
        float4 pre[4];
        if (c < 3) {
            const float* Wn = W + (c + 1) * BKC * HH;
#pragma unroll
            for (int i = 0; i < 4; i++) {
                int idx = tid + i * 256;
                int k = idx >> 5, n4 = idx & 31;
                pre[i] = *(const float4*)&Wn[k * HH + n4 * 4];
            }
        }
        const float* Bc = Bs + (c & 1) * BKC * BSTR;
#pragma unroll
        for (int k4 = 0; k4 < BKC / 4; k4++) {
            float4 a4[8];
#pragma unroll
            for (int rr = 0; rr < 8; rr++)
                a4[rr] = *(const float4*)&As[(m0 + lane_r + 4 * rr) * ASTR + k4 * 4 + c * BKC];
#pragma unroll
            for (int kj = 0; kj < 4; kj++) {
                float4 b0 = *(const float4*)&Bc[(k4 * 4 + kj) * BSTR + n0];
                float4 b1 = *(const float4*)&Bc[(k4 * 4 + kj) * BSTR + n0 + 4];
#pragma unroll
                for (int rr = 0; rr < 8; rr++) {
                    float av = (&a4[rr].x)[kj];
                    acc[rr][0] += av * b0.x; acc[rr][1] += av * b0.y;
                    acc[rr][2] += av * b0.z; acc[rr][3] += av * b0.w;
                    acc[rr][4] += av * b1.x; acc[rr][5] += av * b1.y;
                    acc[rr][6] += av * b1.z; acc[rr][7] += av * b1.w;
                }
            }
        }
        if (c < 3) {
            float* Bn = Bs + ((c + 1) & 1) * BKC * BSTR;
#pragma unroll
            for (int i = 0; i < 4; i++) {
                int idx = tid + i * 256;
                int k = idx >> 5, n4 = idx & 31;
                *(float4*)&Bn[k * BSTR + n4 * 4] = pre[i];
            }
        }
        __syncthreads();
    }

    // ---------- epilogue: dst = src_row + relu((1-beta)*xx + beta*acc) ----------
    float omb = 1.0f - beta;
#pragma unroll
    for (int rr = 0; rr < 8; rr++) {
        int ml = m0 + lane_r + 4 * rr;
        int row = r0 + ml;
        if (row < NN) {
            float4 xv0 = *(const float4*)&As[ml * ASTR + n0];
            float4 xv1 = *(const float4*)&As[ml * ASTR + n0 + 4];
            const float* srp = &src[(size_t)row * HH + n0];
            float4 cv0 = *(const float4*)srp;
            float4 cv1 = *(const float4*)(srp + 4);
            cv0.x += fmaxf(omb * xv0.x + beta * acc[rr][0], 0.f);
            cv0.y += fmaxf(omb * xv0.y + beta * acc[rr][1], 0.f);
            cv0.z += fmaxf(omb * xv0.z + beta * acc[rr][2], 0.f);
            cv0.w += fmaxf(omb * xv0.w + beta * acc[rr][3], 0.f);
            cv1.x += fmaxf(omb * xv1.x + beta * acc[rr][4], 0.f);
            cv1.y += fmaxf(omb * xv1.y + beta * acc[rr][5], 0.f);
            cv1.z += fmaxf(omb * xv1.z + beta * acc[rr][6], 0.f);
            cv1.w += fmaxf(omb * xv1.w + beta * acc[rr][7], 0.f);
            float* dsp = &dst[(size_t)row * HH + n0];
            *(float4*)dsp = cv0;
            *(float4*)(dsp + 4) = cv1;
        }
    }
}

// ---------------- output projection: out = xc @ W_out^T + b_out ----------------
__global__ void out_proj_kernel(const float* __restrict__ xc,
                                const float* __restrict__ Wout,
                                const float* __restrict__ bout,
                                float* __restrict__ out) {
    int gt = blockIdx.x * blockDim.x + threadIdx.x;
    int row = gt >> 5;
    int lane = threadIdx.x & 31;
    if (row >= NN) return;
    float4 v = ((const float4*)xc)[row * 32 + lane];
#pragma unroll
    for (int c = 0; c < 3; c++) {
        float4 w = *(const float4*)&Wout[c * HH + lane * 4];
        float s = v.x * w.x + v.y * w.y + v.z * w.z + v.w * w.w;
#pragma unroll
        for (int o = 16; o; o >>= 1) s += __shfl_down_sync(0xFFFFFFFFu, s, o);
        if (lane == 0) out[row * 3 + c] = s + bout[c];
    }
}

extern "C" void kernel_launch(void* const* d_in, const int* in_sizes, int n_in,
                              void* d_out, int out_size) {
    const float* x    = (const float*)d_in[0];
    const int*   er   = (const int*)d_in[1];
    const int*   ec   = (const int*)d_in[2];
    const float* ew   = (const float*)d_in[3];
    const float* Win  = (const float*)d_in[4];
    const float* bin  = (const float*)d_in[5];
    const float* Wout = (const float*)d_in[6];
    const float* bout = (const float*)d_in[7];
    const float* Wc   = (const float*)d_in[8];
    float* out = (float*)d_out;

    cudaFuncSetAttribute(layer_fused_kernel,
                         cudaFuncAttributeMaxDynamicSharedMemorySize, SMEM_FUSED);

    float* bufA; cudaGetSymbolAddress((void**)&bufA, g_xca);
    float* bufB; cudaGetSymbolAddress((void**)&bufB, g_xcb);

    input_proj_kernel<<<NN / 32, 128>>>(x, Win, bin);
    zero_cnt_kernel<<<(NN + 255) / 256, 256>>>();
    scatter_ell_kernel<<<(EE + 255) / 256, 256>>>(er, ec, ew);

    for (int l = 0; l < LL; l++) {
        float beta = logf(0.5f / (float)(l + 1) + 1.0f);
        const float* src = (l & 1) ? bufB : bufA;
        float* dst = (l & 1) ? bufA : bufB;
        layer_fused_kernel<<<NP / 128, 256, SMEM_FUSED>>>(src, dst,
                                                          Wc + (size_t)l * HH * HH, beta);
    }

    out_proj_kernel<<<(NN * 32 + 255) / 256, 256>>>(bufA, Wout, bout, out);
}

// round 7
// speedup vs baseline: 1.0973x; 1.0973x over previous
#include <cuda_runtime.h>
#include <math.h>
#include <stdint.h>

#define NN   40000
#define NP   40064          // 313 * 128, padded
#define EE   640000
#define FIN  33
#define HH   128
#define LL   8
#define ALPHA 0.1f
#define DEGCAP 64

// ---------------- scratch (no allocation allowed) ----------------
__device__ float g_x0[NP * HH];
__device__ float g_xca[NP * HH];           // ping
__device__ float g_xcb[NP * HH];           // pong
__device__ float g_xx[NP * HH];            // aggregation output (pad rows stay 0)
__device__ float g_wp[LL * HH * HH];       // W' = (1-beta) I + beta W
__device__ int   g_cnt[NN];
__device__ int   g_ecol[(size_t)NN * DEGCAP];
__device__ float g_ew[(size_t)NN * DEGCAP];

// ---------------- input projection: x0 = relu(x @ W_in^T + b_in) ----------------
__global__ void input_proj_kernel(const float* __restrict__ x,
                                  const float* __restrict__ Win,
                                  const float* __restrict__ bin) {
    __shared__ float sW[HH * FIN];
    __shared__ float sx[FIN];
    int tid = threadIdx.x;
    for (int i = tid; i < HH * FIN; i += 128) sW[i] = Win[i];
    float b = bin[tid];
    int row0 = blockIdx.x * 32;
    for (int r = 0; r < 32; r++) {
        int row = row0 + r;
        __syncthreads();
        if (tid < FIN) sx[tid] = x[row * FIN + tid];
        __syncthreads();
        float s = b;
#pragma unroll
        for (int f = 0; f < FIN; f++) s += sW[tid * FIN + f] * sx[f];
        s = fmaxf(s, 0.0f);
        g_x0[row * HH + tid] = s;
        g_xca[row * HH + tid] = s;
    }
}

// ---------------- W' = beta*W + (1-beta)*I, per layer ----------------
__global__ void wprep_kernel(const float* __restrict__ Wc) {
    int idx = blockIdx.x * blockDim.x + threadIdx.x;
    if (idx >= LL * HH * HH) return;
    int l = idx >> 14;                 // HH*HH = 16384
    int rem = idx & 16383;
    int k = rem >> 7, n = rem & 127;
    float beta = logf(0.5f / (float)(l + 1) + 1.0f);
    float v = beta * Wc[idx];
    if (k == n) v += 1.0f - beta;
    g_wp[idx] = v;
}

// ---------------- ELL build ----------------
__global__ void zero_cnt_kernel() {
    int i = blockIdx.x * blockDim.x + threadIdx.x;
    if (i < NN) g_cnt[i] = 0;
}

__global__ void scatter_ell_kernel(const int* __restrict__ er,
                                   const int* __restrict__ ec,
                                   const float* __restrict__ ew) {
    int e = blockIdx.x * blockDim.x + threadIdx.x;
    if (e < EE) {
        int r = er[e];
        int s = atomicAdd(&g_cnt[r], 1);
        if (s < DEGCAP) {
            g_ecol[(size_t)r * DEGCAP + s] = ec[e];
            g_ew[(size_t)r * DEGCAP + s] = ew[e];
        }
    }
}

// ---------------- SpMM: g_xx = 0.9 * (A @ src) + 0.1 * x0 ----------------
// one warp per row, lane owns 4 contiguous features, 4-edge unroll (MLP 4)
__global__ void spmm_kernel(const float* __restrict__ src) {
    int gt = blockIdx.x * blockDim.x + threadIdx.x;
    int row = gt >> 5;
    int lane = threadIdx.x & 31;
    if (row >= NN) return;
    int cn = g_cnt[row];
    cn = cn < DEGCAP ? cn : DEGCAP;
    const int* cb = g_ecol + (size_t)row * DEGCAP;
    const float* wb = g_ew + (size_t)row * DEGCAP;
    const float4* s4 = (const float4*)src;

    float4 a0 = make_float4(0.f, 0.f, 0.f, 0.f);
    float4 a1 = a0, a2 = a0, a3 = a0;
    int i = 0;
    for (; i + 4 <= cn; i += 4) {
        int4 c = *(const int4*)&cb[i];
        float4 w = *(const float4*)&wb[i];
        float4 v0 = s4[c.x * 32 + lane];
        float4 v1 = s4[c.y * 32 + lane];
        float4 v2 = s4[c.z * 32 + lane];
        float4 v3 = s4[c.w * 32 + lane];
        a0.x += w.x * v0.x; a0.y += w.x * v0.y; a0.z += w.x * v0.z; a0.w += w.x * v0.w;
        a1.x += w.y * v1.x; a1.y += w.y * v1.y; a1.z += w.y * v1.z; a1.w += w.y * v1.w;
        a2.x += w.z * v2.x; a2.y += w.z * v2.y; a2.z += w.z * v2.z; a2.w += w.z * v2.w;
        a3.x += w.w * v3.x; a3.y += w.w * v3.y; a3.z += w.w * v3.z; a3.w += w.w * v3.w;
    }
    for (; i < cn; i++) {
        int c = cb[i];
        float w = wb[i];
        float4 v = s4[c * 32 + lane];
        a0.x += w * v.x; a0.y += w * v.y; a0.z += w * v.z; a0.w += w * v.w;
    }
    a0.x += a1.x + a2.x + a3.x;
    a0.y += a1.y + a2.y + a3.y;
    a0.z += a1.z + a2.z + a3.z;
    a0.w += a1.w + a2.w + a3.w;

    float4 x0v = ((const float4*)g_x0)[row * 32 + lane];
    float4 o;
    o.x = (1.0f - ALPHA) * a0.x + ALPHA * x0v.x;
    o.y = (1.0f - ALPHA) * a0.y + ALPHA * x0v.y;
    o.z = (1.0f - ALPHA) * a0.z + ALPHA * x0v.z;
    o.w = (1.0f - ALPHA) * a0.w + ALPHA * x0v.w;
    ((float4*)g_xx)[row * 32 + lane] = o;
}

// ---------------- GEMM: dst = src + relu(g_xx @ W') ----------------
// 256 threads = 8 warps (4m x 2n), thread tile 8x8.
// B (W', 128x128) fully resident in smem; A double-buffered in 32-k chunks.
#define GASTR 36
#define GBSTR 132
#define GBK   32
#define SMEM_GEMM ((2 * 128 * GASTR + 128 * GBSTR) * 4)

__global__ void __launch_bounds__(256, 2) gemm_kernel(const float* __restrict__ src,
                                                      float* __restrict__ dst,
                                                      const float* __restrict__ Wp) {
    extern __shared__ float sm[];
    float* As = sm;                        // [2][128][GASTR]
    float* Bs = sm + 2 * 128 * GASTR;      // [128][GBSTR]

    int tid = threadIdx.x;
    int wid = tid >> 5, lane = tid & 31;
    int r0 = blockIdx.x * 128;
    const float* Ag = g_xx + (size_t)r0 * HH;

    // load full B = W' (4096 float4, 16 per thread)
#pragma unroll
    for (int i = 0; i < 16; i++) {
        int idx = tid + i * 256;
        int k = idx >> 5, n4 = idx & 31;
        float4 v = *(const float4*)&Wp[k * HH + n4 * 4];
        *(float4*)&Bs[k * GBSTR + n4 * 4] = v;
    }
    // load A chunk 0
#pragma unroll
    for (int i = 0; i < 4; i++) {
        int idx = tid + i * 256;
        int m = idx >> 3, k4 = idx & 7;
        float4 v = *(const float4*)&Ag[m * HH + k4 * 4];
        *(float4*)&As[m * GASTR + k4 * 4] = v;
    }
    __syncthreads();

    int wm = wid >> 1, wn = wid & 1;
    int lane_r = lane >> 3, lane_c = lane & 7;
    int m0 = wm * 32, n0 = wn * 64 + lane_c * 8;

    float acc[8][8];
#pragma unroll
    for (int i = 0; i < 8; i++)
#pragma unroll
        for (int j = 0; j < 8; j++) acc[i][j] = 0.f;

#pragma unroll
    for (int c = 0; c < 4; c++) {
        float4 pre[4];
        if (c < 3) {
            const float* An = Ag + (c + 1) * GBK;
#pragma unroll
            for (int i = 0; i < 4; i++) {
                int idx = tid + i * 256;
                int m = idx >> 3, k4 = idx & 7;
                pre[i] = *(const float4*)&An[m * HH + k4 * 4];
            }
        }
        const float* Ac = As + (c & 1) * 128 * GASTR;
#pragma unroll
        for (int k4 = 0; k4 < GBK / 4; k4++) {
            float4 a4[8];
#pragma unroll
            for (int rr = 0; rr < 8; rr++)
                a4[rr] = *(const float4*)&Ac[(m0 + lane_r + 4 * rr) * GASTR + k4 * 4];
#pragma unroll
            for (int kj = 0; kj < 4; kj++) {
                int kk = c * GBK + k4 * 4 + kj;
                float4 b0 = *(const float4*)&Bs[kk * GBSTR + n0];
                float4 b1 = *(const float4*)&Bs[kk * GBSTR + n0 + 4];
#pragma unroll
                for (int rr = 0; rr < 8; rr++) {
                    float av = (&a4[rr].x)[kj];
                    acc[rr][0] += av * b0.x; acc[rr][1] += av * b0.y;
                    acc[rr][2] += av * b0.z; acc[rr][3] += av * b0.w;
                    acc[rr][4] += av * b1.x; acc[rr][5] += av * b1.y;
                    acc[rr][6] += av * b1.z; acc[rr][7] += av * b1.w;
                }
            }
        }
        if (c < 3) {
            float* An = As + ((c + 1) & 1) * 128 * GASTR;
#pragma unroll
            for (int i = 0; i < 4; i++) {
                int idx = tid + i * 256;
                int m = idx >> 3, k4 = idx & 7;
                *(float4*)&An[m * GASTR + k4 * 4] = pre[i];
            }
            __syncthreads();
        }
    }

    // epilogue: dst = src + relu(acc)
#pragma unroll
    for (int rr = 0; rr < 8; rr++) {
        int row = r0 + m0 + lane_r + 4 * rr;
        const float* srp = &src[(size_t)row * HH + n0];
        float4 cv0 = *(const float4*)srp;
        float4 cv1 = *(const float4*)(srp + 4);
        cv0.x += fmaxf(acc[rr][0], 0.f);
        cv0.y += fmaxf(acc[rr][1], 0.f);
        cv0.z += fmaxf(acc[rr][2], 0.f);
        cv0.w += fmaxf(acc[rr][3], 0.f);
        cv1.x += fmaxf(acc[rr][4], 0.f);
        cv1.y += fmaxf(acc[rr][5], 0.f);
        cv1.z += fmaxf(acc[rr][6], 0.f);
        cv1.w += fmaxf(acc[rr][7], 0.f);
        float* dsp = &dst[(size_t)row * HH + n0];
        *(float4*)dsp = cv0;
        *(float4*)(dsp + 4) = cv1;
    }
}

// ---------------- output projection: out = xc @ W_out^T + b_out ----------------
__global__ void out_proj_kernel(const float* __restrict__ xc,
                                const float* __restrict__ Wout,
                                const float* __restrict__ bout,
                                float* __restrict__ out) {
    int gt = blockIdx.x * blockDim.x + threadIdx.x;
    int row = gt >> 5;
    int lane = threadIdx.x & 31;
    if (row >= NN) return;
    float4 v = ((const float4*)xc)[row * 32 + lane];
#pragma unroll
    for (int c = 0; c < 3; c++) {
        float4 w = *(const float4*)&Wout[c * HH + lane * 4];
        float s = v.x * w.x + v.y * w.y + v.z * w.z + v.w * w.w;
#pragma unroll
        for (int o = 16; o; o >>= 1) s += __shfl_down_sync(0xFFFFFFFFu, s, o);
        if (lane == 0) out[row * 3 + c] = s + bout[c];
    }
}

extern "C" void kernel_launch(void* const* d_in, const int* in_sizes, int n_in,
                              void* d_out, int out_size) {
    const float* x    = (const float*)d_in[0];
    const int*   er   = (const int*)d_in[1];
    const int*   ec   = (const int*)d_in[2];
    const float* ew   = (const float*)d_in[3];
    const float* Win  = (const float*)d_in[4];
    const float* bin  = (const float*)d_in[5];
    const float* Wout = (const float*)d_in[6];
    const float* bout = (const float*)d_in[7];
    const float* Wc   = (const float*)d_in[8];
    float* out = (float*)d_out;

    cudaFuncSetAttribute(gemm_kernel,
                         cudaFuncAttributeMaxDynamicSharedMemorySize, SMEM_GEMM);

    float* bufA; cudaGetSymbolAddress((void**)&bufA, g_xca);
    float* bufB; cudaGetSymbolAddress((void**)&bufB, g_xcb);
    float* wp;   cudaGetSymbolAddress((void**)&wp, g_wp);

    input_proj_kernel<<<NN / 32, 128>>>(x, Win, bin);
    wprep_kernel<<<(LL * HH * HH + 255) / 256, 256>>>(Wc);
    zero_cnt_kernel<<<(NN + 255) / 256, 256>>>();
    scatter_ell_kernel<<<(EE + 255) / 256, 256>>>(er, ec, ew);

    for (int l = 0; l < LL; l++) {
        const float* src = (l & 1) ? bufB : bufA;
        float* dst = (l & 1) ? bufA : bufB;
        spmm_kernel<<<(NN * 32 + 255) / 256, 256>>>(src);
        gemm_kernel<<<NP / 128, 256, SMEM_GEMM>>>(src, dst, wp + (size_t)l * HH * HH);
    }

    out_proj_kernel<<<(NN * 32 + 255) / 256, 256>>>(bufA, Wout, bout, out);
}

// round 9
// speedup vs baseline: 1.4056x; 1.2810x over previous
#include <cuda_runtime.h>
#include <cuda_fp16.h>
#include <math.h>
#include <stdint.h>

#define NN   40000
#define NP   40064          // 313 * 128, padded
#define EE   640000
#define FIN  33
#define HH   128
#define LL   8
#define ALPHA 0.1f
#define DEGCAP 64

// ---------------- scratch (no allocation allowed) ----------------
__device__ float  g_x0[NP * HH];
__device__ float  g_xca[NP * HH];           // fp32 ping
__device__ float  g_xcb[NP * HH];           // fp32 pong
__device__ __half g_xha[NP * HH];           // fp16 scaled mirror ping
__device__ __half g_xhb[NP * HH];           // fp16 scaled mirror pong
__device__ float  g_xx[NP * HH];            // aggregation output (pad rows stay 0)
__device__ float  g_wp[LL * HH * HH];       // W' = (1-beta) I + beta W
__device__ int    g_cnt[NN];
__device__ int    g_ecol[(size_t)NN * DEGCAP];
__device__ float  g_ew[(size_t)NN * DEGCAP];

// ---------------- W' prep + zero cnt (launch 0) ----------------
__global__ void wprep_zero_kernel(const float* __restrict__ Wc) {
    int idx = blockIdx.x * blockDim.x + threadIdx.x;
    if (idx < NN) g_cnt[idx] = 0;
    if (idx < LL * HH * HH) {
        int l = idx >> 14;
        int rem = idx & 16383;
        int k = rem >> 7, n = rem & 127;
        float beta = logf(0.5f / (float)(l + 1) + 1.0f);
        float v = beta * Wc[idx];
        if (k == n) v += 1.0f - beta;
        g_wp[idx] = v;
    }
}

// ---------------- input projection: x0 = relu(x @ W_in^T + b_in) (launch 1) ------
// mirror scale for layer-0 spmm is 2^0 = 1
__global__ void input_proj_kernel(const float* __restrict__ x,
                                  const float* __restrict__ Win,
                                  const float* __restrict__ bin) {
    __shared__ float sW[HH * FIN];
    __shared__ float sx[FIN];
    int tid = threadIdx.x;
    for (int i = tid; i < HH * FIN; i += 128) sW[i] = Win[i];
    float b = bin[tid];
    int row0 = blockIdx.x * 32;
    for (int r = 0; r < 32; r++) {
        int row = row0 + r;
        __syncthreads();
        if (tid < FIN) sx[tid] = x[row * FIN + tid];
        __syncthreads();
        float s = b;
#pragma unroll
        for (int f = 0; f < FIN; f++) s += sW[tid * FIN + f] * sx[f];
        s = fmaxf(s, 0.0f);
        g_x0[row * HH + tid] = s;
        g_xca[row * HH + tid] = s;
        g_xha[row * HH + tid] = __float2half_rn(s);
    }
}

// ---------------- ELL scatter (launch 2) ----------------
__global__ void scatter_ell_kernel(const int* __restrict__ er,
                                   const int* __restrict__ ec,
                                   const float* __restrict__ ew) {
    int e = blockIdx.x * blockDim.x + threadIdx.x;
    if (e < EE) {
        int r = er[e];
        int s = atomicAdd(&g_cnt[r], 1);
        if (s < DEGCAP) {
            g_ecol[(size_t)r * DEGCAP + s] = ec[e];
            g_ew[(size_t)r * DEGCAP + s] = ew[e];
        }
    }
}

// ---------------- SpMM: g_xx = invs * (A @ srcH) + 0.1 * x0 (launch 3 profiled) --
// srcH holds xc * 2^{-3l}; invs = 0.9 * 2^{3l} undoes the scale exactly.
// one warp per row, lane owns 4 contiguous features (2x half2), 4-edge unroll
__global__ void spmm_kernel(const __half* __restrict__ srcH, float invs) {
    int gt = blockIdx.x * blockDim.x + threadIdx.x;
    int row = gt >> 5;
    int lane = threadIdx.x & 31;
    if (row >= NN) return;
    int cn = g_cnt[row];
    cn = cn < DEGCAP ? cn : DEGCAP;
    const int* cb = g_ecol + (size_t)row * DEGCAP;
    const float* wb = g_ew + (size_t)row * DEGCAP;
    const __half2* s2 = (const __half2*)srcH;   // row stride 64 half2
    int l2 = lane * 2;

    float4 a0 = make_float4(0.f, 0.f, 0.f, 0.f);
    float4 a1 = a0, a2 = a0, a3 = a0;
    int i = 0;
    for (; i + 4 <= cn; i += 4) {
        int4 c = *(const int4*)&cb[i];
        float4 w = *(const float4*)&wb[i];
        __half2 p0a = s2[c.x * 64 + l2], p0b = s2[c.x * 64 + l2 + 1];
        __half2 p1a = s2[c.y * 64 + l2], p1b = s2[c.y * 64 + l2 + 1];
        __half2 p2a = s2[c.z * 64 + l2], p2b = s2[c.z * 64 + l2 + 1];
        __half2 p3a = s2[c.w * 64 + l2], p3b = s2[c.w * 64 + l2 + 1];
        float2 f0a = __half22float2(p0a), f0b = __half22float2(p0b);
        float2 f1a = __half22float2(p1a), f1b = __half22float2(p1b);
        float2 f2a = __half22float2(p2a), f2b = __half22float2(p2b);
        float2 f3a = __half22float2(p3a), f3b = __half22float2(p3b);
        a0.x += w.x * f0a.x; a0.y += w.x * f0a.y; a0.z += w.x * f0b.x; a0.w += w.x * f0b.y;
        a1.x += w.y * f1a.x; a1.y += w.y * f1a.y; a1.z += w.y * f1b.x; a1.w += w.y * f1b.y;
        a2.x += w.z * f2a.x; a2.y += w.z * f2a.y; a2.z += w.z * f2b.x; a2.w += w.z * f2b.y;
        a3.x += w.w * f3a.x; a3.y += w.w * f3a.y; a3.z += w.w * f3b.x; a3.w += w.w * f3b.y;
    }
    for (; i < cn; i++) {
        int c = cb[i];
        float w = wb[i];
        float2 fa = __half22float2(s2[c * 64 + l2]);
        float2 fb = __half22float2(s2[c * 64 + l2 + 1]);
        a0.x += w * fa.x; a0.y += w * fa.y; a0.z += w * fb.x; a0.w += w * fb.y;
    }
    a0.x += a1.x + a2.x + a3.x;
    a0.y += a1.y + a2.y + a3.y;
    a0.z += a1.z + a2.z + a3.z;
    a0.w += a1.w + a2.w + a3.w;

    float4 x0v = ((const float4*)g_x0)[row * 32 + lane];
    float4 o;
    o.x = invs * a0.x + ALPHA * x0v.x;
    o.y = invs * a0.y + ALPHA * x0v.y;
    o.z = invs * a0.z + ALPHA * x0v.z;
    o.w = invs * a0.w + ALPHA * x0v.w;
    ((float4*)g_xx)[row * 32 + lane] = o;
}

// ---------------- GEMM: dst = src + relu(g_xx @ W'); mirror = dst * hscale -------
// round-1 proven shape: BM=64, BN=128, BK=16, 256 threads, 8x4 thread tile
__global__ void __launch_bounds__(256) gemm_kernel(const float* __restrict__ src,
                                                   float* __restrict__ dst,
                                                   __half* __restrict__ dstH,
                                                   const float* __restrict__ Wp,
                                                   float hscale) {
    __shared__ float As[16][68];
    __shared__ float Bs[16][128];
    int tid = threadIdx.x;
    int tx = tid & 31;
    int ty = tid >> 5;
    int r0 = blockIdx.x * 64;
    const float* Ag = g_xx + (size_t)r0 * HH;

    float acc[8][4];
#pragma unroll
    for (int i = 0; i < 8; i++)
#pragma unroll
        for (int j = 0; j < 4; j++) acc[i][j] = 0.f;

    for (int k0 = 0; k0 < HH; k0 += 16) {
        {
            int m = tid >> 2, kq = tid & 3;
            float4 v = *(const float4*)&Ag[m * HH + k0 + kq * 4];
            As[kq * 4 + 0][m] = v.x;
            As[kq * 4 + 1][m] = v.y;
            As[kq * 4 + 2][m] = v.z;
            As[kq * 4 + 3][m] = v.w;
        }
        {
#pragma unroll
            for (int i = 0; i < 2; i++) {
                int idx = tid * 2 + i;
                int k = idx >> 5, c4 = idx & 31;
                *(float4*)&Bs[k][c4 * 4] = *(const float4*)&Wp[(k0 + k) * HH + c4 * 4];
            }
        }
        __syncthreads();
#pragma unroll
        for (int k = 0; k < 16; k++) {
            float4 a0 = *(const float4*)&As[k][ty * 8];
            float4 a1 = *(const float4*)&As[k][ty * 8 + 4];
            float4 bb = *(const float4*)&Bs[k][tx * 4];
            float av[8] = {a0.x, a0.y, a0.z, a0.w, a1.x, a1.y, a1.z, a1.w};
#pragma unroll
            for (int rr = 0; rr < 8; rr++) {
                acc[rr][0] += av[rr] * bb.x;
                acc[rr][1] += av[rr] * bb.y;
                acc[rr][2] += av[rr] * bb.z;
                acc[rr][3] += av[rr] * bb.w;
            }
        }
        __syncthreads();
    }

    // epilogue: dst = src + relu(acc); mirror = dst * hscale (exact pow2 scale)
#pragma unroll
    for (int rr = 0; rr < 8; rr++) {
        int row = r0 + ty * 8 + rr;
        const float* srp = &src[(size_t)row * HH + tx * 4];
        float4 cv = *(const float4*)srp;
        cv.x += fmaxf(acc[rr][0], 0.f);
        cv.y += fmaxf(acc[rr][1], 0.f);
        cv.z += fmaxf(acc[rr][2], 0.f);
        cv.w += fmaxf(acc[rr][3], 0.f);
        *(float4*)&dst[(size_t)row * HH + tx * 4] = cv;
        __half2 h0 = __floats2half2_rn(cv.x * hscale, cv.y * hscale);
        __half2 h1 = __floats2half2_rn(cv.z * hscale, cv.w * hscale);
        uint2 hp;
        hp.x = *(const unsigned*)&h0;
        hp.y = *(const unsigned*)&h1;
        *(uint2*)&dstH[(size_t)row * HH + tx * 4] = hp;
    }
}

// ---------------- output projection: out = xc @ W_out^T + b_out ----------------
__global__ void out_proj_kernel(const float* __restrict__ xc,
                                const float* __restrict__ Wout,
                                const float* __restrict__ bout,
                                float* __restrict__ out) {
    int gt = blockIdx.x * blockDim.x + threadIdx.x;
    int row = gt >> 5;
    int lane = threadIdx.x & 31;
    if (row >= NN) return;
    float4 v = ((const float4*)xc)[row * 32 + lane];
#pragma unroll
    for (int c = 0; c < 3; c++) {
        float4 w = *(const float4*)&Wout[c * HH + lane * 4];
        float s = v.x * w.x + v.y * w.y + v.z * w.z + v.w * w.w;
#pragma unroll
        for (int o = 16; o; o >>= 1) s += __shfl_down_sync(0xFFFFFFFFu, s, o);
        if (lane == 0) out[row * 3 + c] = s + bout[c];
    }
}

extern "C" void kernel_launch(void* const* d_in, const int* in_sizes, int n_in,
                              void* d_out, int out_size) {
    const float* x    = (const float*)d_in[0];
    const int*   er   = (const int*)d_in[1];
    const int*   ec   = (const int*)d_in[2];
    const float* ew   = (const float*)d_in[3];
    const float* Win  = (const float*)d_in[4];
    const float* bin  = (const float*)d_in[5];
    const float* Wout = (const float*)d_in[6];
    const float* bout = (const float*)d_in[7];
    const float* Wc   = (const float*)d_in[8];
    float* out = (float*)d_out;

    float*  bufA; cudaGetSymbolAddress((void**)&bufA, g_xca);
    float*  bufB; cudaGetSymbolAddress((void**)&bufB, g_xcb);
    __half* hbufA; cudaGetSymbolAddress((void**)&hbufA, g_xha);
    __half* hbufB; cudaGetSymbolAddress((void**)&hbufB, g_xhb);
    float*  wp;   cudaGetSymbolAddress((void**)&wp, g_wp);

    wprep_zero_kernel<<<(LL * HH * HH + 255) / 256, 256>>>(Wc);      // launch 0
    input_proj_kernel<<<NN / 32, 128>>>(x, Win, bin);                // launch 1
    scatter_ell_kernel<<<(EE + 255) / 256, 256>>>(er, ec, ew);       // launch 2

    for (int l = 0; l < LL; l++) {
        const float*  src  = (l & 1) ? bufB : bufA;
        float*        dst  = (l & 1) ? bufA : bufB;
        const __half* srcH = (l & 1) ? hbufB : hbufA;
        __half*       dstH = (l & 1) ? hbufA : hbufB;
        float invs = ldexpf(0.9f, 3 * l);            // 0.9 * 2^{3l}
        float hscale = ldexpf(1.0f, -3 * (l + 1));   // 2^{-3(l+1)}
        spmm_kernel<<<(NN * 32 + 255) / 256, 256>>>(srcH, invs);     // launch 3 on l=0
        gemm_kernel<<<NP / 64, 256>>>(src, dst, dstH,
                                      wp + (size_t)l * HH * HH, hscale);
    }

    out_proj_kernel<<<(NN * 32 + 255) / 256, 256>>>(bufA, Wout, bout, out);
}

// round 11
// speedup vs baseline: 1.7385x; 1.2368x over previous
#include <cuda_runtime.h>
#include <cuda_fp16.h>
#include <math.h>
#include <stdint.h>

#define NN   40000
#define NP   40064          // 313 * 128, padded
#define EE   640000
#define FIN  33
#define HH   128
#define LL   8
#define ALPHA 0.1f
#define DEGCAP 64

// ---------------- scratch (no allocation allowed) ----------------
__device__ float  g_x0[NP * HH];
__device__ float  g_xca[NP * HH];           // fp32 ping
__device__ float  g_xcb[NP * HH];           // fp32 pong
__device__ __half g_xha[NP * HH];           // fp16 scaled mirror ping
__device__ __half g_xhb[NP * HH];           // fp16 scaled mirror pong
__device__ float  g_xx[NP * HH];            // aggregation output (pad rows stay 0)
__device__ float  g_wp[LL * HH * HH];       // W' = (1-beta) I + beta W
__device__ int    g_cnt[NN];
__device__ int    g_ecol[(size_t)NN * DEGCAP];
__device__ float  g_ew[(size_t)NN * DEGCAP];

// ---------------- packed f32x2 helpers (SASS FFMA2) ----------------
__device__ __forceinline__ unsigned long long pack_dup(float v) {
    unsigned long long r;
    unsigned u = __float_as_uint(v);
    asm("mov.b64 %0, {%1, %1};" : "=l"(r) : "r"(u));
    return r;
}
__device__ __forceinline__ void fma2(unsigned long long& d, unsigned long long a,
                                     unsigned long long b) {
    asm("fma.rn.f32x2 %0, %1, %2, %3;" : "=l"(d) : "l"(a), "l"(b), "l"(d));
}
__device__ __forceinline__ void unpack2(unsigned long long v, float& lo, float& hi) {
    unsigned ul, uh;
    asm("mov.b64 {%0, %1}, %2;" : "=r"(ul), "=r"(uh) : "l"(v));
    lo = __uint_as_float(ul);
    hi = __uint_as_float(uh);
}

// ---------------- W' prep + zero cnt ----------------
__global__ void wprep_zero_kernel(const float* __restrict__ Wc) {
    int idx = blockIdx.x * blockDim.x + threadIdx.x;
    if (idx < NN) g_cnt[idx] = 0;
    if (idx < LL * HH * HH) {
        int l = idx >> 14;
        int rem = idx & 16383;
        int k = rem >> 7, n = rem & 127;
        float beta = logf(0.5f / (float)(l + 1) + 1.0f);
        float v = beta * Wc[idx];
        if (k == n) v += 1.0f - beta;
        g_wp[idx] = v;
    }
}

// ---------------- input projection: x0 = relu(x @ W_in^T + b_in) ----------------
__global__ void input_proj_kernel(const float* __restrict__ x,
                                  const float* __restrict__ Win,
                                  const float* __restrict__ bin) {
    __shared__ float sW[HH * FIN];
    __shared__ float sx[FIN];
    int tid = threadIdx.x;
    for (int i = tid; i < HH * FIN; i += 128) sW[i] = Win[i];
    float b = bin[tid];
    int row0 = blockIdx.x * 32;
    for (int r = 0; r < 32; r++) {
        int row = row0 + r;
        __syncthreads();
        if (tid < FIN) sx[tid] = x[row * FIN + tid];
        __syncthreads();
        float s = b;
#pragma unroll
        for (int f = 0; f < FIN; f++) s += sW[tid * FIN + f] * sx[f];
        s = fmaxf(s, 0.0f);
        g_x0[row * HH + tid] = s;
        g_xca[row * HH + tid] = s;
        g_xha[row * HH + tid] = __float2half_rn(s);   // scale 2^0 for layer 0
    }
}

// ---------------- ELL scatter ----------------
__global__ void scatter_ell_kernel(const int* __restrict__ er,
                                   const int* __restrict__ ec,
                                   const float* __restrict__ ew) {
    int e = blockIdx.x * blockDim.x + threadIdx.x;
    if (e < EE) {
        int r = er[e];
        int s = atomicAdd(&g_cnt[r], 1);
        if (s < DEGCAP) {
            g_ecol[(size_t)r * DEGCAP + s] = ec[e];
            g_ew[(size_t)r * DEGCAP + s] = ew[e];
        }
    }
}

// ---------------- SpMM: g_xx = invs * (A @ srcH) + 0.1 * x0 ----------------
// 2 rows per warp: 16 lanes per row, lane owns 8 fp16 feats (one LDG.128/edge).
__device__ __forceinline__ void acc8(float* a, uint4 d, float w) {
    float2 f0 = __half22float2(*(__half2*)&d.x);
    float2 f1 = __half22float2(*(((__half2*)&d.x) + 1));
    float2 f2 = __half22float2(*(__half2*)&d.z);
    float2 f3 = __half22float2(*(((__half2*)&d.z) + 1));
    a[0] += w * f0.x; a[1] += w * f0.y;
    a[2] += w * f1.x; a[3] += w * f1.y;
    a[4] += w * f2.x; a[5] += w * f2.y;
    a[6] += w * f3.x; a[7] += w * f3.y;
}

__global__ void spmm_kernel(const __half* __restrict__ srcH, float invs) {
    int gt = blockIdx.x * blockDim.x + threadIdx.x;
    int warp = gt >> 5;
    int lane = threadIdx.x & 31;
    int hsel = lane >> 4;          // which of the 2 rows
    int hl = lane & 15;            // feature group: 8 halfs at hl*8
    int row = warp * 2 + hsel;
    if (row >= NN) return;
    int cn = g_cnt[row];
    cn = cn < DEGCAP ? cn : DEGCAP;
    const int* cb = g_ecol + (size_t)row * DEGCAP;
    const float* wb = g_ew + (size_t)row * DEGCAP;

    float aA[8] = {0.f, 0.f, 0.f, 0.f, 0.f, 0.f, 0.f, 0.f};
    float aB[8] = {0.f, 0.f, 0.f, 0.f, 0.f, 0.f, 0.f, 0.f};
    int fo = hl * 8;
    int i = 0;
    for (; i + 4 <= cn; i += 4) {
        int4 c = *(const int4*)&cb[i];
        float4 w = *(const float4*)&wb[i];
        uint4 d0 = *(const uint4*)&srcH[(size_t)c.x * HH + fo];
        uint4 d1 = *(const uint4*)&srcH[(size_t)c.y * HH + fo];
        uint4 d2 = *(const uint4*)&srcH[(size_t)c.z * HH + fo];
        uint4 d3 = *(const uint4*)&srcH[(size_t)c.w * HH + fo];
        acc8(aA, d0, w.x);
        acc8(aB, d1, w.y);
        acc8(aA, d2, w.z);
        acc8(aB, d3, w.w);
    }
    for (; i < cn; i++) {
        int c = cb[i];
        float w = wb[i];
        uint4 d = *(const uint4*)&srcH[(size_t)c * HH + fo];
        acc8(aA, d, w);
    }
#pragma unroll
    for (int j = 0; j < 8; j++) aA[j] += aB[j];

    const float* x0p = &g_x0[(size_t)row * HH + fo];
    float4 x00 = *(const float4*)x0p;
    float4 x01 = *(const float4*)(x0p + 4);
    float4 o0, o1;
    o0.x = invs * aA[0] + ALPHA * x00.x;
    o0.y = invs * aA[1] + ALPHA * x00.y;
    o0.z = invs * aA[2] + ALPHA * x00.z;
    o0.w = invs * aA[3] + ALPHA * x00.w;
    o1.x = invs * aA[4] + ALPHA * x01.x;
    o1.y = invs * aA[5] + ALPHA * x01.y;
    o1.z = invs * aA[6] + ALPHA * x01.z;
    o1.w = invs * aA[7] + ALPHA * x01.w;
    float* xxp = &g_xx[(size_t)row * HH + fo];
    *(float4*)xxp = o0;
    *(float4*)(xxp + 4) = o1;
}

// ---------------- GEMM (FFMA2): dst = src + relu(g_xx @ W'); fp16 mirror ---------
// BM=64, BN=128, BK=16, 256 threads; warp = 8 rows (A broadcast), lane = 4 cols.
// acc as 4 m-pairs x 4 n in packed f32x2.
__global__ void __launch_bounds__(256) gemm_kernel(const float* __restrict__ src,
                                                   float* __restrict__ dst,
                                                   __half* __restrict__ dstH,
                                                   const float* __restrict__ Wp,
                                                   float hscale) {
    __shared__ float As[16][68];
    __shared__ float Bs[16][128];
    int tid = threadIdx.x;
    int tx = tid & 31;
    int ty = tid >> 5;
    int r0 = blockIdx.x * 64;
    const float* Ag = g_xx + (size_t)r0 * HH;

    unsigned long long acc2[4][4];
#pragma unroll
    for (int p = 0; p < 4; p++)
#pragma unroll
        for (int c = 0; c < 4; c++) acc2[p][c] = 0ULL;   // (+0.f, +0.f)

    for (int k0 = 0; k0 < HH; k0 += 16) {
        {
            int m = tid >> 2, kq = tid & 3;
            float4 v = *(const float4*)&Ag[m * HH + k0 + kq * 4];
            As[kq * 4 + 0][m] = v.x;
            As[kq * 4 + 1][m] = v.y;
            As[kq * 4 + 2][m] = v.z;
            As[kq * 4 + 3][m] = v.w;
        }
        {
#pragma unroll
            for (int i = 0; i < 2; i++) {
                int idx = tid * 2 + i;
                int k = idx >> 5, c4 = idx & 31;
                *(float4*)&Bs[k][c4 * 4] = *(const float4*)&Wp[(k0 + k) * HH + c4 * 4];
            }
        }
        __syncthreads();
#pragma unroll
        for (int k = 0; k < 16; k++) {
            // A: 8 consecutive m as 4 aligned f32x2 pairs (broadcast across warp)
            ulonglong2 a01 = *(const ulonglong2*)&As[k][ty * 8];
            ulonglong2 a23 = *(const ulonglong2*)&As[k][ty * 8 + 4];
            float4 bb = *(const float4*)&Bs[k][tx * 4];
            unsigned long long bd0 = pack_dup(bb.x);
            unsigned long long bd1 = pack_dup(bb.y);
            unsigned long long bd2 = pack_dup(bb.z);
            unsigned long long bd3 = pack_dup(bb.w);
            fma2(acc2[0][0], a01.x, bd0); fma2(acc2[0][1], a01.x, bd1);
            fma2(acc2[0][2], a01.x, bd2); fma2(acc2[0][3], a01.x, bd3);
            fma2(acc2[1][0], a01.y, bd0); fma2(acc2[1][1], a01.y, bd1);
            fma2(acc2[1][2], a01.y, bd2); fma2(acc2[1][3], a01.y, bd3);
            fma2(acc2[2][0], a23.x, bd0); fma2(acc2[2][1], a23.x, bd1);
            fma2(acc2[2][2], a23.x, bd2); fma2(acc2[2][3], a23.x, bd3);
            fma2(acc2[3][0], a23.y, bd0); fma2(acc2[3][1], a23.y, bd1);
            fma2(acc2[3][2], a23.y, bd2); fma2(acc2[3][3], a23.y, bd3);
        }
        __syncthreads();
    }

    // epilogue: pair p holds rows (2p, 2p+1) of this thread's 8-row group
#pragma unroll
    for (int p = 0; p < 4; p++) {
        float lo0, hi0, lo1, hi1, lo2, hi2, lo3, hi3;
        unpack2(acc2[p][0], lo0, hi0);
        unpack2(acc2[p][1], lo1, hi1);
        unpack2(acc2[p][2], lo2, hi2);
        unpack2(acc2[p][3], lo3, hi3);
        int rowe = r0 + ty * 8 + 2 * p;
#pragma unroll
        for (int h = 0; h < 2; h++) {
            int row = rowe + h;
            float v0 = h ? hi0 : lo0;
            float v1 = h ? hi1 : lo1;
            float v2 = h ? hi2 : lo2;
            float v3 = h ? hi3 : lo3;
            const float* srp = &src[(size_t)row * HH + tx * 4];
            float4 cv = *(const float4*)srp;
            cv.x += fmaxf(v0, 0.f);
            cv.y += fmaxf(v1, 0.f);
            cv.z += fmaxf(v2, 0.f);
            cv.w += fmaxf(v3, 0.f);
            *(float4*)&dst[(size_t)row * HH + tx * 4] = cv;
            __half2 h0 = __floats2half2_rn(cv.x * hscale, cv.y * hscale);
            __half2 h1 = __floats2half2_rn(cv.z * hscale, cv.w * hscale);
            uint2 hp;
            hp.x = *(const unsigned*)&h0;
            hp.y = *(const unsigned*)&h1;
            *(uint2*)&dstH[(size_t)row * HH + tx * 4] = hp;
        }
    }
}

// ---------------- output projection: out = xc @ W_out^T + b_out ----------------
__global__ void out_proj_kernel(const float* __restrict__ xc,
                                const float* __restrict__ Wout,
                                const float* __restrict__ bout,
                                float* __restrict__ out) {
    int gt = blockIdx.x * blockDim.x + threadIdx.x;
    int row = gt >> 5;
    int lane = threadIdx.x & 31;
    if (row >= NN) return;
    float4 v = ((const float4*)xc)[row * 32 + lane];
#pragma unroll
    for (int c = 0; c < 3; c++) {
        float4 w = *(const float4*)&Wout[c * HH + lane * 4];
        float s = v.x * w.x + v.y * w.y + v.z * w.z + v.w * w.w;
#pragma unroll
        for (int o = 16; o; o >>= 1) s += __shfl_down_sync(0xFFFFFFFFu, s, o);
        if (lane == 0) out[row * 3 + c] = s + bout[c];
    }
}

extern "C" void kernel_launch(void* const* d_in, const int* in_sizes, int n_in,
                              void* d_out, int out_size) {
    const float* x    = (const float*)d_in[0];
    const int*   er   = (const int*)d_in[1];
    const int*   ec   = (const int*)d_in[2];
    const float* ew   = (const float*)d_in[3];
    const float* Win  = (const float*)d_in[4];
    const float* bin  = (const float*)d_in[5];
    const float* Wout = (const float*)d_in[6];
    const float* bout = (const float*)d_in[7];
    const float* Wc   = (const float*)d_in[8];
    float* out = (float*)d_out;

    float*  bufA; cudaGetSymbolAddress((void**)&bufA, g_xca);
    float*  bufB; cudaGetSymbolAddress((void**)&bufB, g_xcb);
    __half* hbufA; cudaGetSymbolAddress((void**)&hbufA, g_xha);
    __half* hbufB; cudaGetSymbolAddress((void**)&hbufB, g_xhb);
    float*  wp;   cudaGetSymbolAddress((void**)&wp, g_wp);

    wprep_zero_kernel<<<(LL * HH * HH + 255) / 256, 256>>>(Wc);
    input_proj_kernel<<<NN / 32, 128>>>(x, Win, bin);
    scatter_ell_kernel<<<(EE + 255) / 256, 256>>>(er, ec, ew);

    for (int l = 0; l < LL; l++) {
        const float*  src  = (l & 1) ? bufB : bufA;
        float*        dst  = (l & 1) ? bufA : bufB;
        const __half* srcH = (l & 1) ? hbufB : hbufA;
        __half*       dstH = (l & 1) ? hbufA : hbufB;
        float invs = ldexpf(0.9f, 3 * l);            // 0.9 * 2^{3l}
        float hscale = ldexpf(1.0f, -3 * (l + 1));   // 2^{-3(l+1)}
        spmm_kernel<<<(NN / 2 * 32 + 255) / 256, 256>>>(srcH, invs);  // launch 3 on l=0
        gemm_kernel<<<NP / 64, 256>>>(src, dst, dstH,
                                      wp + (size_t)l * HH * HH, hscale);
    }

    out_proj_kernel<<<(NN * 32 + 255) / 256, 256>>>(bufA, Wout, bout, out);
}